// round 6
// baseline (speedup 1.0000x reference)
#include <cuda_runtime.h>

#define BATCH 512
#define SEQ   200
#define TT    10
#define EMB   25
#define HH    64
#define G3    192          // 3*H
#define BT    7            // batch rows per GRU block
#define BLK_PER_DIR 74     // ceil(512/7)

// ---------------- scratch (static device memory; no allocation) ----------------
__device__ float g_xpf[SEQ * BATCH * G3];   // [s][b][192] forward input proj
__device__ float g_xpb[SEQ * BATCH * G3];   // [s][b][192] backward input proj
__device__ float g_hsf[SEQ * BATCH * HH];   // [s][b][64]
__device__ float g_hsb[SEQ * BATCH * HH];   // [s][b][64] (stored at original s)
__device__ float g_hT [BATCH * HH];
__device__ float g_mask[SEQ * BATCH];       // [s][b] step mask as float

// ---------------- f32x2 helpers ----------------
__device__ __forceinline__ unsigned long long pack2(float lo, float hi) {
    unsigned long long r;
    asm("mov.b64 %0, {%1, %2};" : "=l"(r) : "r"(__float_as_uint(lo)), "r"(__float_as_uint(hi)));
    return r;
}
__device__ __forceinline__ void unpack2(unsigned long long v, float& lo, float& hi) {
    unsigned int a, b;
    asm("mov.b64 {%0, %1}, %2;" : "=r"(a), "=r"(b) : "l"(v));
    lo = __uint_as_float(a); hi = __uint_as_float(b);
}
__device__ __forceinline__ unsigned long long fma2(unsigned long long a, unsigned long long b,
                                                   unsigned long long c) {
    unsigned long long d;
    asm("fma.rn.f32x2 %0, %1, %2, %3;" : "=l"(d) : "l"(a), "l"(b), "l"(c));
    return d;
}

// accurate-enough fast activations (ex2.approx based, ~1e-6 rel err; saturates safely)
__device__ __forceinline__ float sigx(float x) {
    return __fdividef(1.0f, 1.0f + __expf(-x));
}
__device__ __forceinline__ float tanhx(float x) {
    return fmaf(2.0f, sigx(2.0f * x), -1.0f);
}

// =====================================================================
// Kernel A: embedding gather + masked mean + both input projections
//   rows = b*SEQ + s, 32 rows per block.
// =====================================================================
__global__ __launch_bounds__(256) void kA(const int* __restrict__ inp,
                                          const float* __restrict__ emb,
                                          const float* __restrict__ Wf,
                                          const float* __restrict__ bf,
                                          const float* __restrict__ Wb,
                                          const float* __restrict__ bb) {
    __shared__ __align__(16) float2 xs2[32][EMB];   // x duplicated (x,x)
    const int tid = threadIdx.x;
    const int base = blockIdx.x * 32;

    // gather + masked mean
    for (int o = tid; o < 32 * EMB; o += 256) {
        int r = o / EMB, e = o - r * EMB;
        const int* ip = inp + (size_t)(base + r) * TT;
        float sum = 0.0f; int cnt = 0;
#pragma unroll
        for (int t = 0; t < TT; t++) {
            int idx = ip[t];
            if (idx != 0) { sum += emb[(size_t)idx * EMB + e]; cnt++; }
        }
        float x = sum / (float)(cnt > 0 ? cnt : 1);
        xs2[r][e] = make_float2(x, x);
    }
    // step mask
    for (int o = tid; o < 32; o += 256) {
        int row = base + o;
        int b = row / SEQ, s = row - b * SEQ;
        g_mask[s * BATCH + b] = (inp[(size_t)row * TT] != 0) ? 1.0f : 0.0f;
    }
    __syncthreads();

    if (tid < G3) {
        const int c = tid;
        unsigned long long w2[EMB];           // (W_f[k][c], W_b[k][c])
#pragma unroll
        for (int k = 0; k < EMB; k++) w2[k] = pack2(Wf[k * G3 + c], Wb[k * G3 + c]);
        const unsigned long long bias2 = pack2(bf[c], bb[c]);   // row 0 of b_f/b_b
        for (int r = 0; r < 32; r++) {
            const unsigned long long* xp = (const unsigned long long*)xs2[r];
            unsigned long long a0 = bias2;
            unsigned long long a1 = pack2(0.0f, 0.0f);
#pragma unroll
            for (int k = 0; k + 1 < EMB; k += 2) {
                a0 = fma2(xp[k], w2[k], a0);
                a1 = fma2(xp[k + 1], w2[k + 1], a1);
            }
            a0 = fma2(xp[EMB - 1], w2[EMB - 1], a0);   // EMB=25 odd tail
            float l0, h0, l1, h1;
            unpack2(a0, l0, h0); unpack2(a1, l1, h1);
            int row = base + r;
            int b = row / SEQ, s = row - b * SEQ;
            size_t off = ((size_t)s * BATCH + b) * G3 + c;
            g_xpf[off] = l0 + l1;
            g_xpb[off] = h0 + h1;
        }
    }
}

// =====================================================================
// Kernel B: bidirectional GRU scans. grid = 2*74 = 148 blocks, 512 thr.
//   Per block: 7 batch rows, 200 sequential steps.
//   Matvec: tid<384, two column groups (192 cols each), U in registers,
//   k-packed f32x2, h broadcast from SMEM.
//   Gates: tid<448, thread = (row, j).
// =====================================================================
__global__ __launch_bounds__(512) void kB(const float* __restrict__ Uf,
                                          const float* __restrict__ bf,
                                          const float* __restrict__ Ub,
                                          const float* __restrict__ bb) {
    __shared__ __align__(16) float sh[BT][HH];
    __shared__ __align__(16) float srec[BT][G3];

    const int tid = threadIdx.x;
    const int dir = blockIdx.x / BLK_PER_DIR;
    const int tile = blockIdx.x - dir * BLK_PER_DIR;
    const int b0 = tile * BT;

    const float* U    = dir ? Ub : Uf;
    const float* brec = (dir ? bb : bf) + G3;        // recurrent bias row
    const float* xp   = dir ? g_xpb : g_xpf;
    float* hs         = dir ? g_hsb : g_hsf;

    const int c   = tid % G3;
    const int grp = tid / G3;               // 0 / 1 valid matvec groups
    const bool mv = tid < 2 * G3;           // 384 matvec threads

    unsigned long long u2[HH / 2];
    float biasc = 0.0f;
    if (mv) {
#pragma unroll
        for (int kk = 0; kk < HH / 2; kk++)
            u2[kk] = pack2(U[(2 * kk) * G3 + c], U[(2 * kk + 1) * G3 + c]);
        biasc = brec[c];
    }

    const int gr = tid / HH, j = tid % HH;  // gate role
    const bool gate = tid < BT * HH;        // 448
    const int bb_ = b0 + gr;
    const bool gv = gate && (bb_ < BATCH);

    if (gate) sh[gr][j] = 0.0f;
    __syncthreads();

    for (int si = 0; si < SEQ; si++) {
        const int s = dir ? (SEQ - 1 - si) : si;

        // prefetch xp + mask (independent of h; hides DRAM behind the matvec)
        float xz = 0.0f, xr = 0.0f, xh = 0.0f, m = 0.0f;
        if (gv) {
            size_t o = ((size_t)s * BATCH + bb_) * G3 + j;
            xz = xp[o]; xr = xp[o + HH]; xh = xp[o + 2 * HH];
            m = g_mask[s * BATCH + bb_];
        }

        if (mv) {
#pragma unroll
            for (int r = 0; r < BT; r++) {
                if ((r & 1) != grp) continue;     // group 0: rows 0,2,4,6; group 1: 1,3,5
                const unsigned long long* hp = (const unsigned long long*)sh[r];
                unsigned long long a0 = pack2(biasc, 0.0f);
                unsigned long long a1 = pack2(0.0f, 0.0f);
#pragma unroll
                for (int kk = 0; kk < HH / 2; kk += 2) {
                    a0 = fma2(hp[kk],     u2[kk],     a0);
                    a1 = fma2(hp[kk + 1], u2[kk + 1], a1);
                }
                float l0, h0, l1, h1;
                unpack2(a0, l0, h0); unpack2(a1, l1, h1);
                srec[r][c] = (l0 + h0) + (l1 + h1);
            }
        }
        __syncthreads();

        if (gv) {
            float rz = srec[gr][j], rr = srec[gr][HH + j], rh = srec[gr][2 * HH + j];
            float z  = sigx(xz + rz);
            float rg = sigx(xr + rr);
            float hhv = tanhx(xh + rg * rh);
            float hold = sh[gr][j];
            float hn = z * hold + (1.0f - z) * hhv;
            hn = hold + m * (hn - hold);            // masked update
            sh[gr][j] = hn;
            hs[((size_t)s * BATCH + bb_) * HH + j] = hn;
        }
        __syncthreads();
    }

    if (dir == 0 && gv) g_hT[bb_ * HH + j] = sh[gr][j];
}

// =====================================================================
// Kernel C: attention. grid = 512 (one block per batch), 256 threads.
//   keys matvec: thread = (s-lane, k-half, j), W_k half-column in regs,
//   k-packed f32x2 with out broadcast from SMEM.
// =====================================================================
__global__ __launch_bounds__(256) void kC(const float* __restrict__ Wk,
                                          const float* __restrict__ bk,
                                          const float* __restrict__ Wq,
                                          const float* __restrict__ bq,
                                          const float* __restrict__ We,
                                          const float* __restrict__ be,
                                          float* __restrict__ out) {
    __shared__ __align__(16) float sout[8][2 * HH];   // 8 timesteps of concat out
    __shared__ float spp[8][2][HH];                   // partial keys per k-half
    __shared__ float sq[HH], sbk[HH], sWe[HH];
    __shared__ float se[SEQ];
    __shared__ float sinv;

    const int tid = threadIdx.x;
    const int b = blockIdx.x;

    const int sl = tid / 128;            // 0/1 : handles s_local [sl*4, sl*4+4)
    const int inner = tid & 127;
    const int kh = inner / HH;           // 0/1 : k in [kh*64, kh*64+64)
    const int j = inner & (HH - 1);

    unsigned long long w2[32];           // (W_k[k][j], W_k[k+1][j]) for my half
#pragma unroll
    for (int t = 0; t < 32; t++)
        w2[t] = pack2(Wk[(kh * HH + 2 * t) * HH + j], Wk[(kh * HH + 2 * t + 1) * HH + j]);

    if (tid < HH) {
        float q = bq[tid];
#pragma unroll
        for (int k = 0; k < HH; k++) q += g_hT[b * HH + k] * Wq[k * HH + tid];
        sq[tid] = q;
        sbk[tid] = bk[tid];
        sWe[tid] = We[tid];
    }
    __syncthreads();

    const float be0 = be[0];

    for (int ch = 0; ch < SEQ / 8; ch++) {
        const int s0 = ch * 8;
        // stage out[s0..s0+8) into SMEM
        for (int o = tid; o < 8 * 2 * HH; o += 256) {
            int sl_ = o >> 7, k = o & 127;
            size_t off = ((size_t)(s0 + sl_) * BATCH + b) * HH;
            sout[sl_][k] = (k < HH) ? g_hsf[off + k] : g_hsb[off + (k - HH)];
        }
        __syncthreads();

        float p[4];
#pragma unroll
        for (int ss = 0; ss < 4; ss++) {
            const unsigned long long* op =
                (const unsigned long long*)(&sout[sl * 4 + ss][kh * HH]);
            unsigned long long a0 = pack2(0.0f, 0.0f), a1 = pack2(0.0f, 0.0f);
#pragma unroll
            for (int t = 0; t < 32; t += 2) {
                a0 = fma2(op[t],     w2[t],     a0);
                a1 = fma2(op[t + 1], w2[t + 1], a1);
            }
            float l0, h0, l1, h1;
            unpack2(a0, l0, h0); unpack2(a1, l1, h1);
            p[ss] = (l0 + h0) + (l1 + h1);
        }
#pragma unroll
        for (int ss = 0; ss < 4; ss++) spp[sl * 4 + ss][kh][j] = p[ss];
        __syncthreads();

        // e_s = tanh(key + q) . We + be  (one warp per timestep)
        {
            const int sidx = tid / 32, lane = tid & 31;
            float acc = 0.0f;
#pragma unroll
            for (int h = 0; h < 2; h++) {
                int jj = lane + h * 32;
                float key = spp[sidx][0][jj] + spp[sidx][1][jj] + sbk[jj];
                acc += tanhx(key + sq[jj]) * sWe[jj];
            }
#pragma unroll
            for (int off = 16; off > 0; off >>= 1)
                acc += __shfl_xor_sync(0xFFFFFFFFu, acc, off);
            if (lane == 0) {
                int s = s0 + sidx;
                float m = g_mask[s * BATCH + b];
                se[s] = acc + be0 + (1.0f - m) * (-1e9f);
            }
        }
        __syncthreads();
    }

    // softmax over S (one warp)
    if (tid < 32) {
        float mx = -1e30f;
        for (int s = tid; s < SEQ; s += 32) mx = fmaxf(mx, se[s]);
#pragma unroll
        for (int off = 16; off > 0; off >>= 1)
            mx = fmaxf(mx, __shfl_xor_sync(0xFFFFFFFFu, mx, off));
        float sum = 0.0f;
        for (int s = tid; s < SEQ; s += 32) {
            float pz = __expf(se[s] - mx);
            se[s] = pz; sum += pz;
        }
#pragma unroll
        for (int off = 16; off > 0; off >>= 1)
            sum += __shfl_xor_sync(0xFFFFFFFFu, sum, off);
        if (tid == 0) sinv = __fdividef(1.0f, sum);
    }
    __syncthreads();

    // context = sum_s w_s * out_s
    if (tid < 2 * HH) {
        const int k = tid;
        const float* src = (k < HH) ? (g_hsf + (size_t)b * HH + k)
                                    : (g_hsb + (size_t)b * HH + (k - HH));
        float ctx = 0.0f;
#pragma unroll 4
        for (int s = 0; s < SEQ; s++)
            ctx += se[s] * src[(size_t)s * (BATCH * HH)];
        out[b * (2 * HH) + k] = ctx * sinv;
    }
}

// =====================================================================
extern "C" void kernel_launch(void* const* d_in, const int* in_sizes, int n_in,
                              void* d_out, int out_size) {
    const int*   inp = (const int*)d_in[0];
    const float* emb = (const float*)d_in[1];
    const float* Wf  = (const float*)d_in[2];
    const float* Uf  = (const float*)d_in[3];
    const float* bf  = (const float*)d_in[4];
    const float* Wb  = (const float*)d_in[5];
    const float* Ub  = (const float*)d_in[6];
    const float* bb  = (const float*)d_in[7];
    const float* Wk  = (const float*)d_in[8];
    const float* bk  = (const float*)d_in[9];
    const float* Wq  = (const float*)d_in[10];
    const float* bq  = (const float*)d_in[11];
    const float* We  = (const float*)d_in[12];
    const float* be  = (const float*)d_in[13];
    float* out = (float*)d_out;

    kA<<<(BATCH * SEQ) / 32, 256>>>(inp, emb, Wf, bf, Wb, bb);
    kB<<<2 * BLK_PER_DIR, 512>>>(Uf, bf, Ub, bb);
    kC<<<BATCH, 256>>>(Wk, bk, Wq, bq, We, be, out);
}